// round 15
// baseline (speedup 1.0000x reference)
#include <cuda_runtime.h>
#include <cuda_fp16.h>
#include <math.h>

#define Hd 1024
#define Dm 512
#define Vn 50257
#define Sn 128
#define An 1024
#define Tn 25
#define SOS 1
#define RPB 16                       /* logits rows per block (2 per warp) */
#define NB3 ((Vn + RPB - 1) / RPB)   /* 3142 logits blocks (proven shape) */
#define NB0 ((Vn + 7) / 8)           /* 6283 step-0 blocks */
#define NBP ((Vn + 63) / 64)         /* 786 gemmP blocks */
#define NBS 128                      /* small-kernel blocks (co-resident) */
#define NTS 768                      /* small-kernel threads (24 warps) */

// ---------------- persistent device scratch ----------------
__device__ float g_hbuf[2][Hd];
__device__ float g_attn[An];              // used by step 0 only
__device__ float g_gh[3 * Hd];            // Whh @ hn + bhh, produced by logits(t)
__device__ float g_scoreslot[2][Sn];      // atomic score accum, parity-buffered
__device__ unsigned g_scnt[2];            // producer counters, parity-buffered
__device__ float g_M[Sn][Hd];             // emb @ Wq  (per launch)
__device__ float g_logZ;
__device__ unsigned long long g_apk[2];   // packed argmax, per parity
__device__ float g_sum[2];                // sum exp(logit), per parity
__device__ __half g_Wh[(size_t)Vn * 2048];    // fp16 Wout (206 MB)
__device__ __half g_P[(size_t)Vn * Sn];       // P = Wout_a @ emb^T  (12.9 MB)
__device__ __half g_emb_h[Sn * An];           // fp16 emb
__device__ __half g_Wih_h[3 * Hd * Dm];       // fp16 Wih
__device__ __half g_Whh_h[3 * Hd * Hd];       // fp16 Whh
__device__ unsigned g_cnt = 0;
__device__ volatile unsigned g_gen = 0;

__device__ __forceinline__ float warp_sum(float v) {
#pragma unroll
    for (int o = 16; o > 0; o >>= 1) v += __shfl_down_sync(0xffffffffu, v, o);
    return v;
}
__device__ __forceinline__ unsigned long long umaxll(unsigned long long a, unsigned long long b) {
    return a > b ? a : b;
}
__device__ __forceinline__ float dot16(uint4 u, float4 ma, float4 mb) {
    const __half2* hp = (const __half2*)&u;
    float2 f0 = __half22float2(hp[0]);
    float2 f1 = __half22float2(hp[1]);
    float2 f2 = __half22float2(hp[2]);
    float2 f3 = __half22float2(hp[3]);
    return f0.x*ma.x + f0.y*ma.y + f1.x*ma.z + f1.y*ma.w
         + f2.x*mb.x + f2.y*mb.y + f3.x*mb.z + f3.y*mb.w;
}
__device__ __forceinline__ unsigned long long packkey(float logit, int v) {
    unsigned b = __float_as_uint(logit);
    unsigned key = (b & 0x80000000u) ? ~b : (b | 0x80000000u);
    return ((unsigned long long)key << 32) |
           (unsigned long long)(0xFFFFFFFFu - (unsigned)v);
}

// grid barrier: NBS blocks co-resident (used at step 0 only)
__device__ __forceinline__ void gsync() {
    __syncthreads();
    if (threadIdx.x == 0) {
        __threadfence();
        unsigned gen = g_gen;
        if (atomicAdd(&g_cnt, 1u) == NBS - 1) {
            g_cnt = 0;
            __threadfence();
            g_gen = gen + 1;
        } else {
            while (g_gen == gen) { __nanosleep(64); }
        }
        __threadfence();
    }
    __syncthreads();
}

// ------------- K0: GRU weights fp32 -> fp16 (once per launch) -------------
__device__ void cvt8(const float* __restrict__ src, __half* __restrict__ dst, size_t n8,
                     size_t base, size_t stride)
{
    for (size_t i = base; i < n8; i += stride) {
        const float4* s4 = (const float4*)src + 2 * i;
        float4 a = s4[0], b = s4[1];
        uint4 u;
        ((__half2*)&u)[0] = __floats2half2_rn(a.x, a.y);
        ((__half2*)&u)[1] = __floats2half2_rn(a.z, a.w);
        ((__half2*)&u)[2] = __floats2half2_rn(b.x, b.y);
        ((__half2*)&u)[3] = __floats2half2_rn(b.z, b.w);
        ((uint4*)dst)[i] = u;
    }
}

__global__ void k_convert(const float* __restrict__ Wih, const float* __restrict__ Whh)
{
    size_t base = (size_t)blockIdx.x * blockDim.x + threadIdx.x;
    size_t stride = (size_t)gridDim.x * blockDim.x;
    cvt8(Wih, g_Wih_h, (size_t)3 * Hd * Dm / 8, base, stride);
    cvt8(Whh, g_Whh_h, (size_t)3 * Hd * Hd / 8, base, stride);
}

// ------ K0b: M = emb @ Wq, emb->fp16, slot/counter reset (once per launch) ------
__global__ void k_prep(const float* __restrict__ emb, const float* __restrict__ Wq)
{
    if (blockIdx.x == 0) {
        if (threadIdx.x < Sn) {
            g_scoreslot[0][threadIdx.x] = 0.f;
            g_scoreslot[1][threadIdx.x] = 0.f;
        }
        if (threadIdx.x == 0) { g_scnt[0] = 0u; g_scnt[1] = 0u; }
    }
    {
        const int b = blockIdx.x;
        for (int i = threadIdx.x; i < An; i += 128)
            g_emb_h[b * An + i] = __float2half(emb[(size_t)b * An + i]);
    }
    __shared__ float scol[8][Hd];
    const int hbase = blockIdx.x * 8;
    for (int idx = threadIdx.x; idx < 8 * Hd; idx += 128) {
        int c = idx & 7, a = idx >> 3;
        scol[c][a] = Wq[(size_t)a * Hd + hbase + c];
    }
    __syncthreads();
    const int s = threadIdx.x;
    float acc[8] = {0.f, 0.f, 0.f, 0.f, 0.f, 0.f, 0.f, 0.f};
    const float4* e4 = (const float4*)(emb + (size_t)s * An);
    for (int a4 = 0; a4 < An / 4; a4++) {
        float4 e = e4[a4];
#pragma unroll
        for (int c = 0; c < 8; c++)
            acc[c] += e.x * scol[c][4 * a4] + e.y * scol[c][4 * a4 + 1]
                    + e.z * scol[c][4 * a4 + 2] + e.w * scol[c][4 * a4 + 3];
    }
#pragma unroll
    for (int c = 0; c < 8; c++) g_M[s][hbase + c] = acc[c];
}

// ------------- K_gemmP: P[v][s] = Wout_a[v] . emb[s]  (tensor cores) -------------
__global__ void __launch_bounds__(128)
k_gemmP()
{
    const int lane = threadIdx.x & 31, w = threadIdx.x >> 5;
    const int v0 = blockIdx.x * 64 + w * 16;
    const int gid = lane >> 2;
    const int qid = lane & 3;
    const int r0 = min(v0 + gid, Vn - 1);
    const int r1 = min(v0 + gid + 8, Vn - 1);
    const __half* A0 = g_Wh + (size_t)r0 * 2048 + 1024 + 2 * qid;
    const __half* A1 = g_Wh + (size_t)r1 * 2048 + 1024 + 2 * qid;

    float c[16][4];
#pragma unroll
    for (int nt = 0; nt < 16; nt++)
        c[nt][0] = c[nt][1] = c[nt][2] = c[nt][3] = 0.f;

    for (int k0 = 0; k0 < An; k0 += 16) {
        unsigned a0 = *(const unsigned*)(A0 + k0);
        unsigned a1 = *(const unsigned*)(A1 + k0);
        unsigned a2 = *(const unsigned*)(A0 + k0 + 8);
        unsigned a3 = *(const unsigned*)(A1 + k0 + 8);
        const __half* B = g_emb_h + (size_t)gid * An + k0 + 2 * qid;
#pragma unroll
        for (int nt = 0; nt < 16; nt++) {
            unsigned b0 = *(const unsigned*)(B + (size_t)nt * 8 * An);
            unsigned b1 = *(const unsigned*)(B + (size_t)nt * 8 * An + 8);
            asm volatile(
                "mma.sync.aligned.m16n8k16.row.col.f32.f16.f16.f32 "
                "{%0,%1,%2,%3}, {%4,%5,%6,%7}, {%8,%9}, {%0,%1,%2,%3};"
                : "+f"(c[nt][0]), "+f"(c[nt][1]), "+f"(c[nt][2]), "+f"(c[nt][3])
                : "r"(a0), "r"(a1), "r"(a2), "r"(a3), "r"(b0), "r"(b1));
        }
    }
    const int sv0 = v0 + gid, sv1 = v0 + gid + 8;
#pragma unroll
    for (int nt = 0; nt < 16; nt++) {
        int sc_ = nt * 8 + 2 * qid;
        if (sv0 < Vn)
            *(__half2*)&g_P[(size_t)sv0 * Sn + sc_] = __floats2half2_rn(c[nt][0], c[nt][1]);
        if (sv1 < Vn)
            *(__half2*)&g_P[(size_t)sv1 * Sn + sc_] = __floats2half2_rn(c[nt][2], c[nt][3]);
    }
}

// ---- K1: small kernel: finalize + GRU(ih only @t>=1) + scores + softmax ----
__global__ void __launch_bounds__(NTS, 1)
k_small(const float* __restrict__ hidden, const float* __restrict__ emb,
        const float* __restrict__ E, const float* __restrict__ bih,
        const float* __restrict__ bhh, float* __restrict__ out, int step)
{
    const int tid = threadIdx.x, bid = blockIdx.x;
    const int wid = tid >> 5, lane = tid & 31;

    __shared__ float sgi[8][3], sgh[8][3];
    __shared__ float shn[8];

    int word = SOS;
    if (step > 0) {
        unsigned long long best = g_apk[(step - 1) & 1];
        word = (int)(0xFFFFFFFFu - (unsigned)(best & 0xFFFFFFFFull));
        float logZ = logf(g_sum[(step - 1) & 1]);
        if (bid == 0 && tid == 0) {
            g_logZ = logZ;
            out[(size_t)Tn * Vn + (size_t)Tn * Sn + (step - 1)] = (float)word;
        }
        if (step == Tn) {   // tail: finalize last step's log_softmax
            for (int v = bid * NTS + tid; v < Vn; v += NBS * NTS)
                out[(size_t)(step - 1) * Vn + v] -= logZ;
            return;
        }
    }
    if (bid == 0 && tid == 0) { g_apk[step & 1] = 0ull; g_sum[step & 1] = 0.f; }

    const float* h = (step == 0) ? hidden : g_hbuf[(step - 1) & 1];
    float* hn = g_hbuf[step & 1];

    // ===== Phase A: GRU — warp per (unit, gate) =====
    // step 0: full (Wih + Whh).  step >=1: Wih only; gh precomputed by logits(t-1).
    {
        const int ul = wid / 3;
        const int g  = wid % 3;
        const int u  = bid * 8 + ul;
        const int row = g * Hd + u;
        const float4* x4 = (const float4*)(E + (size_t)word * Dm);
        const uint4* wi = (const uint4*)(g_Wih_h + (size_t)row * Dm);
        float si = 0.f;
#pragma unroll
        for (int j = 0; j < 2; j++) {
            int idx = lane + 32 * j;
            si += dot16(wi[idx], x4[2 * idx], x4[2 * idx + 1]);
        }
        if (step == 0) {
            const float4* h4 = (const float4*)h;
            const uint4* wh = (const uint4*)(g_Whh_h + (size_t)row * Hd);
            float sh = 0.f;
#pragma unroll
            for (int j = 0; j < 4; j++) {
                int idx = lane + 32 * j;
                sh += dot16(wh[idx], h4[2 * idx], h4[2 * idx + 1]);
            }
            sh = warp_sum(sh);
            if (lane == 0) sgh[ul][g] = sh + bhh[row];
        }
        si = warp_sum(si);
        if (lane == 0) sgi[ul][g] = si + bih[row];
        __syncthreads();
        if (tid < 8) {
            int u2 = bid * 8 + tid;
            float ghr, ghz, ghn_;
            if (step == 0) { ghr = sgh[tid][0]; ghz = sgh[tid][1]; ghn_ = sgh[tid][2]; }
            else { ghr = g_gh[u2]; ghz = g_gh[Hd + u2]; ghn_ = g_gh[2 * Hd + u2]; }
            float r = 1.f / (1.f + __expf(-(sgi[tid][0] + ghr)));
            float z = 1.f / (1.f + __expf(-(sgi[tid][1] + ghz)));
            float n = tanhf(sgi[tid][2] + r * ghn_);
            float hv = (1.f - z) * n + z * h[u2];
            hn[u2] = hv;
            shn[tid] = hv;
        }
        __syncthreads();
        if (tid < Sn) {
            float4 m0 = *(const float4*)&g_M[tid][bid * 8];
            float4 m1 = *(const float4*)&g_M[tid][bid * 8 + 4];
            float p = m0.x*shn[0] + m0.y*shn[1] + m0.z*shn[2] + m0.w*shn[3]
                    + m1.x*shn[4] + m1.y*shn[5] + m1.z*shn[6] + m1.w*shn[7];
            atomicAdd(&g_scoreslot[step & 1][tid], p);
            __threadfence();
        }
    }

    if (step == 0) {
        gsync();
        if (wid < 8) {
            const float* sc = g_scoreslot[0];
            const int d = bid + NBS * wid;
            float sc0 = sc[lane], sc1 = sc[lane + 32];
            float sc2 = sc[lane + 64], sc3 = sc[lane + 96];
            float mx = fmaxf(fmaxf(sc0, sc1), fmaxf(sc2, sc3));
#pragma unroll
            for (int o = 16; o > 0; o >>= 1)
                mx = fmaxf(mx, __shfl_xor_sync(0xffffffffu, mx, o));
            float e0 = __expf(sc0 - mx), e1 = __expf(sc1 - mx);
            float e2 = __expf(sc2 - mx), e3 = __expf(sc3 - mx);
            float ssum = e0 + e1 + e2 + e3;
#pragma unroll
            for (int o = 16; o > 0; o >>= 1)
                ssum += __shfl_xor_sync(0xffffffffu, ssum, o);
            float inv = 1.f / ssum;
            float part = e0 * inv * emb[(size_t)lane * An + d]
                       + e1 * inv * emb[(size_t)(lane + 32) * An + d]
                       + e2 * inv * emb[(size_t)(lane + 64) * An + d]
                       + e3 * inv * emb[(size_t)(lane + 96) * An + d];
            part = warp_sum(part);
            if (lane == 0) g_attn[d] = part;
            if (d == 0) {
                float* wo = out + (size_t)Tn * Vn;
                wo[lane]      = e0 * inv;
                wo[lane + 32] = e1 * inv;
                wo[lane + 64] = e2 * inv;
                wo[lane + 96] = e3 * inv;
            }
        }
    } else {
        __syncthreads();
        if (tid == 0) atomicAdd(&g_scnt[step & 1], 1u);
        if (bid != 0) return;
        if (tid == 0) {
            while (atomicAdd(&g_scnt[step & 1], 0u) < NBS) { __nanosleep(64); }
            __threadfence();
        }
        __syncthreads();
        if (wid == 0) {
            const float* sc = g_scoreslot[step & 1];
            float sc0 = sc[lane], sc1 = sc[lane + 32];
            float sc2 = sc[lane + 64], sc3 = sc[lane + 96];
            float mx = fmaxf(fmaxf(sc0, sc1), fmaxf(sc2, sc3));
#pragma unroll
            for (int o = 16; o > 0; o >>= 1)
                mx = fmaxf(mx, __shfl_xor_sync(0xffffffffu, mx, o));
            float e0 = __expf(sc0 - mx), e1 = __expf(sc1 - mx);
            float e2 = __expf(sc2 - mx), e3 = __expf(sc3 - mx);
            float ssum = e0 + e1 + e2 + e3;
#pragma unroll
            for (int o = 16; o > 0; o >>= 1)
                ssum += __shfl_xor_sync(0xffffffffu, ssum, o);
            float inv = 1.f / ssum;
            float* wo = out + (size_t)Tn * Vn + (size_t)step * Sn;
            wo[lane]      = e0 * inv;
            wo[lane + 32] = e1 * inv;
            wo[lane + 64] = e2 * inv;
            wo[lane + 96] = e3 * inv;
        }
    }
}

// -- K2: split logits GEMV + gh(t+1) row (steps 1..24) --
__global__ void __launch_bounds__(256)
k_logits(const float* __restrict__ bout, const float* __restrict__ bhh,
         float* __restrict__ out, int step)
{
    __shared__ __align__(16) float shn4[Hd];
    __shared__ __align__(16) float sw[Sn];
    __shared__ unsigned long long spk[8];
    __shared__ float sse[8];
    __shared__ float ghred[8];
    const int tid = threadIdx.x, wid = tid >> 5, lane = tid & 31;
    const float* hn = g_hbuf[step & 1];
    const bool do_gh = (blockIdx.x < 3 * Hd);

    if (blockIdx.x == 0) {
        if (tid < Sn) g_scoreslot[(step + 1) & 1][tid] = 0.f;
        if (tid == 0) g_scnt[(step + 1) & 1] = 0u;
    }
    if (tid < RPB) {
        int pv = blockIdx.x * RPB + tid;
        if (pv < Vn) out[(size_t)(step - 1) * Vn + pv] -= g_logZ;
    }
    ((float4*)shn4)[tid] = ((const float4*)hn)[tid];
    if (tid < Sn) sw[tid] = out[(size_t)Tn * Vn + (size_t)step * Sn + tid];

    // issue gh weight load early (2 KB per block)
    uint2 ghu = make_uint2(0u, 0u);
    if (do_gh)
        ghu = ((const uint2*)(g_Whh_h + (size_t)blockIdx.x * Hd))[tid];
    __syncthreads();

    const int v0 = blockIdx.x * RPB + wid * 2;
    const int v1 = v0 + 1;
    const bool val0 = (v0 < Vn), val1 = (v1 < Vn);
    const int v0c = val0 ? v0 : (Vn - 1);
    const int v1c = val1 ? v1 : (Vn - 1);
    float s0 = 0.f, s1 = 0.f;
    {
        const uint4* w4a = (const uint4*)(g_Wh + (size_t)v0c * 2048);
        const uint4* w4b = (const uint4*)(g_Wh + (size_t)v1c * 2048);
        const float4* m4 = (const float4*)shn4;
#pragma unroll
        for (int j = 0; j < 4; j++) {
            int idx = lane + 32 * j;
            float4 ma = m4[2 * idx], mb = m4[2 * idx + 1];
            s0 += dot16(w4a[idx], ma, mb);
            s1 += dot16(w4b[idx], ma, mb);
        }
        uint2 p0 = *(const uint2*)(g_P + (size_t)v0c * Sn + lane * 4);
        uint2 p1 = *(const uint2*)(g_P + (size_t)v1c * Sn + lane * 4);
        float4 wv = ((const float4*)sw)[lane];
        float2 q0 = __half22float2(*(const __half2*)&p0.x);
        float2 q1 = __half22float2(*(const __half2*)&p0.y);
        s0 += q0.x * wv.x + q0.y * wv.y + q1.x * wv.z + q1.y * wv.w;
        float2 r0_ = __half22float2(*(const __half2*)&p1.x);
        float2 r1_ = __half22float2(*(const __half2*)&p1.y);
        s1 += r0_.x * wv.x + r0_.y * wv.y + r1_.x * wv.z + r1_.y * wv.w;
    }
    s0 = warp_sum(s0);
    s1 = warp_sum(s1);

    // gh(t+1) row: all 256 threads reduce Whh[row] . hn (hn staged in smem)
    if (do_gh) {
        float2 a = __half22float2(((const __half2*)&ghu)[0]);
        float2 b = __half22float2(((const __half2*)&ghu)[1]);
        float4 hv = ((const float4*)shn4)[tid];
        float p = a.x*hv.x + a.y*hv.y + b.x*hv.z + b.y*hv.w;
        p = warp_sum(p);
        if (lane == 0) ghred[wid] = p;
    }

    if (lane == 0) {
        float* lp = out + (size_t)step * Vn;
        unsigned long long pk = 0ull;
        float e = 0.f;
        if (val0) {
            float l0 = s0 + bout[v0];
            lp[v0] = l0;
            pk = packkey(l0, v0);
            e = __expf(l0);
        }
        if (val1) {
            float l1 = s1 + bout[v1];
            lp[v1] = l1;
            pk = umaxll(pk, packkey(l1, v1));
            e += __expf(l1);
        }
        spk[wid] = pk; sse[wid] = e;
    }
    __syncthreads();
    if (tid == 0) {
        unsigned long long best = spk[0];
        float tot = sse[0];
#pragma unroll
        for (int i = 1; i < 8; i++) { best = umaxll(best, spk[i]); tot += sse[i]; }
        atomicMax(&g_apk[step & 1], best);
        atomicAdd(&g_sum[step & 1], tot);
        if (do_gh) {
            float s = 0.f;
#pragma unroll
            for (int i = 0; i < 8; i++) s += ghred[i];
            g_gh[blockIdx.x] = s + bhh[blockIdx.x];
        }
    }
}

// -- K2a: step-0 logits from fp32 Wout + fp16 writeback + gh for step 1 --
__global__ void __launch_bounds__(256)
k_logits0(const float* __restrict__ Wout, const float* __restrict__ bout,
          const float* __restrict__ bhh, float* __restrict__ out)
{
    __shared__ __align__(16) float merge[2 * Hd];
    __shared__ unsigned long long spk[8];
    __shared__ float sse[8];
    __shared__ float ghred[8];
    const int tid = threadIdx.x, wid = tid >> 5, lane = tid & 31;
    const float* hn = g_hbuf[0];
    const bool do_gh = (blockIdx.x < 3 * Hd);

    if (blockIdx.x == 0) {
        if (tid < Sn) g_scoreslot[1][tid] = 0.f;
        if (tid == 0) g_scnt[1] = 0u;
    }
    for (int i = tid; i < Hd; i += 256) { merge[i] = hn[i]; merge[Hd + i] = g_attn[i]; }
    uint2 ghu = make_uint2(0u, 0u);
    if (do_gh)
        ghu = ((const uint2*)(g_Whh_h + (size_t)blockIdx.x * Hd))[tid];
    __syncthreads();

    int v = blockIdx.x * 8 + wid;
    float logit = __int_as_float(0xff800000);
    bool valid = (v < Vn);
    if (valid) {
        const float4* w4 = (const float4*)(Wout + (size_t)v * (2 * Hd));
        uint4* wh = (uint4*)(g_Wh + (size_t)v * (2 * Hd));
        const float4* m4 = (const float4*)merge;
        float s = 0.f;
#pragma unroll
        for (int j = 0; j < 8; j++) {
            int idx = lane + 32 * j;
            float4 a = w4[2 * idx], b = w4[2 * idx + 1];
            float4 ma = m4[2 * idx], mb = m4[2 * idx + 1];
            s += a.x*ma.x + a.y*ma.y + a.z*ma.z + a.w*ma.w
               + b.x*mb.x + b.y*mb.y + b.z*mb.z + b.w*mb.w;
            uint4 u;
            ((__half2*)&u)[0] = __floats2half2_rn(a.x, a.y);
            ((__half2*)&u)[1] = __floats2half2_rn(a.z, a.w);
            ((__half2*)&u)[2] = __floats2half2_rn(b.x, b.y);
            ((__half2*)&u)[3] = __floats2half2_rn(b.z, b.w);
            wh[idx] = u;
        }
        s = warp_sum(s);
        if (lane == 0) {
            logit = s + bout[v];
            out[v] = logit;
        }
    }
    if (do_gh) {
        float2 a = __half22float2(((const __half2*)&ghu)[0]);
        float2 b = __half22float2(((const __half2*)&ghu)[1]);
        float4 hv = ((const float4*)merge)[tid >> 2 == 0 ? tid : tid];  // placeholder
        // hn occupies merge[0..1023]; thread t reads floats [4t, 4t+4)
        hv = *(const float4*)&merge[4 * tid];
        float p = a.x*hv.x + a.y*hv.y + b.x*hv.z + b.y*hv.w;
        p = warp_sum(p);
        if (lane == 0) ghred[wid] = p;
    }
    if (lane == 0) {
        unsigned long long pk = 0ull;
        float e = 0.f;
        if (valid) { pk = packkey(logit, v); e = __expf(logit); }
        spk[wid] = pk; sse[wid] = e;
    }
    __syncthreads();
    if (tid == 0) {
        unsigned long long best = spk[0];
        float tot = sse[0];
#pragma unroll
        for (int i = 1; i < 8; i++) { best = umaxll(best, spk[i]); tot += sse[i]; }
        atomicMax(&g_apk[0], best);
        atomicAdd(&g_sum[0], tot);
        if (do_gh) {
            float s = 0.f;
#pragma unroll
            for (int i = 0; i < 8; i++) s += ghred[i];
            g_gh[blockIdx.x] = s + bhh[blockIdx.x];
        }
    }
}

// ---------------- launcher ----------------
extern "C" void kernel_launch(void* const* d_in, const int* in_sizes, int n_in,
                              void* d_out, int out_size)
{
    const float* hidden = (const float*)d_in[0];
    const float* emb    = (const float*)d_in[1];
    const float* E      = (const float*)d_in[2];
    const float* Wih    = (const float*)d_in[3];
    const float* Whh    = (const float*)d_in[4];
    const float* bih    = (const float*)d_in[5];
    const float* bhh    = (const float*)d_in[6];
    const float* Wq     = (const float*)d_in[7];
    const float* Wout   = (const float*)d_in[8];
    const float* bout   = (const float*)d_in[9];
    float* out = (float*)d_out;

    k_convert<<<512, 256>>>(Wih, Whh);
    k_prep<<<Sn, 128>>>(emb, Wq);
    k_small<<<NBS, NTS>>>(hidden, emb, E, bih, bhh, out, 0);
    k_logits0<<<NB0, 256>>>(Wout, bout, bhh, out);   // + gh for step 1
    k_gemmP<<<NBP, 128>>>();
    for (int t = 1; t < Tn; t++) {
        k_small <<<NBS, NTS>>>(hidden, emb, E, bih, bhh, out, t);
        k_logits<<<NB3, 256>>>(bout, bhh, out, t);
    }
    k_small<<<NBS, NTS>>>(hidden, emb, E, bih, bhh, out, Tn);
}

// round 16
// speedup vs baseline: 1.0638x; 1.0638x over previous
#include <cuda_runtime.h>
#include <cuda_fp16.h>
#include <math.h>

#define Hd 1024
#define Dm 512
#define Vn 50257
#define Sn 128
#define An 1024
#define Tn 25
#define SOS 1
#define RPB 16                       /* logits rows per block (2 per warp) */
#define NB3 ((Vn + RPB - 1) / RPB)   /* 3142 logits blocks (proven shape) */
#define NB0 ((Vn + 7) / 8)           /* 6283 step-0 blocks */
#define NBP ((Vn + 63) / 64)         /* 786 gemmP blocks */
#define NBS 128                      /* small-kernel blocks (co-resident) */
#define NTS 768                      /* small-kernel threads (24 warps) */

// ---------------- persistent device scratch ----------------
__device__ float g_hbuf[2][Hd];
__device__ float g_attn[An];              // used by step 0 only
__device__ float g_scoreslot[2][Sn];      // atomic score accum, parity-buffered
__device__ float g_M[Sn][Hd];             // emb @ Wq  (per launch)
__device__ float g_logZ;
__device__ unsigned long long g_apk[2];   // packed argmax, per parity
__device__ float g_sum[2];                // sum exp(logit), per parity
__device__ __half g_Wh[(size_t)Vn * 2048];    // fp16 Wout (206 MB)
__device__ __half g_P[(size_t)Vn * Sn];       // P = Wout_a @ emb^T  (12.9 MB)
__device__ __half g_emb_h[Sn * An];           // fp16 emb
__device__ __half g_Wih_h[3 * Hd * Dm];       // fp16 Wih
__device__ __half g_Whh_h[3 * Hd * Hd];       // fp16 Whh
__device__ unsigned g_cnt = 0;
__device__ volatile unsigned g_gen = 0;

__device__ __forceinline__ float warp_sum(float v) {
#pragma unroll
    for (int o = 16; o > 0; o >>= 1) v += __shfl_down_sync(0xffffffffu, v, o);
    return v;
}
__device__ __forceinline__ unsigned long long umaxll(unsigned long long a, unsigned long long b) {
    return a > b ? a : b;
}
__device__ __forceinline__ float dot16(uint4 u, float4 ma, float4 mb) {
    const __half2* hp = (const __half2*)&u;
    float2 f0 = __half22float2(hp[0]);
    float2 f1 = __half22float2(hp[1]);
    float2 f2 = __half22float2(hp[2]);
    float2 f3 = __half22float2(hp[3]);
    return f0.x*ma.x + f0.y*ma.y + f1.x*ma.z + f1.y*ma.w
         + f2.x*mb.x + f2.y*mb.y + f3.x*mb.z + f3.y*mb.w;
}
__device__ __forceinline__ unsigned long long packkey(float logit, int v) {
    unsigned b = __float_as_uint(logit);
    unsigned key = (b & 0x80000000u) ? ~b : (b | 0x80000000u);
    return ((unsigned long long)key << 32) |
           (unsigned long long)(0xFFFFFFFFu - (unsigned)v);
}

// grid barrier: NBS blocks co-resident (step 0 only)
__device__ __forceinline__ void gsync() {
    __syncthreads();
    if (threadIdx.x == 0) {
        __threadfence();
        unsigned gen = g_gen;
        if (atomicAdd(&g_cnt, 1u) == NBS - 1) {
            g_cnt = 0;
            __threadfence();
            g_gen = gen + 1;
        } else {
            while (g_gen == gen) { __nanosleep(64); }
        }
        __threadfence();
    }
    __syncthreads();
}

// ------------- K0: GRU weights fp32 -> fp16 (once per launch) -------------
__device__ void cvt8(const float* __restrict__ src, __half* __restrict__ dst, size_t n8,
                     size_t base, size_t stride)
{
    for (size_t i = base; i < n8; i += stride) {
        const float4* s4 = (const float4*)src + 2 * i;
        float4 a = s4[0], b = s4[1];
        uint4 u;
        ((__half2*)&u)[0] = __floats2half2_rn(a.x, a.y);
        ((__half2*)&u)[1] = __floats2half2_rn(a.z, a.w);
        ((__half2*)&u)[2] = __floats2half2_rn(b.x, b.y);
        ((__half2*)&u)[3] = __floats2half2_rn(b.z, b.w);
        ((uint4*)dst)[i] = u;
    }
}

__global__ void k_convert(const float* __restrict__ Wih, const float* __restrict__ Whh)
{
    size_t base = (size_t)blockIdx.x * blockDim.x + threadIdx.x;
    size_t stride = (size_t)gridDim.x * blockDim.x;
    cvt8(Wih, g_Wih_h, (size_t)3 * Hd * Dm / 8, base, stride);
    cvt8(Whh, g_Whh_h, (size_t)3 * Hd * Hd / 8, base, stride);
}

// ------ K0b: M = emb @ Wq, emb->fp16, slot reset (once per launch) ------
__global__ void k_prep(const float* __restrict__ emb, const float* __restrict__ Wq)
{
    if (blockIdx.x == 0 && threadIdx.x < Sn) {
        g_scoreslot[0][threadIdx.x] = 0.f;
        g_scoreslot[1][threadIdx.x] = 0.f;
    }
    {
        const int b = blockIdx.x;
        for (int i = threadIdx.x; i < An; i += 128)
            g_emb_h[b * An + i] = __float2half(emb[(size_t)b * An + i]);
    }
    __shared__ float scol[8][Hd];
    const int hbase = blockIdx.x * 8;
    for (int idx = threadIdx.x; idx < 8 * Hd; idx += 128) {
        int c = idx & 7, a = idx >> 3;
        scol[c][a] = Wq[(size_t)a * Hd + hbase + c];
    }
    __syncthreads();
    const int s = threadIdx.x;
    float acc[8] = {0.f, 0.f, 0.f, 0.f, 0.f, 0.f, 0.f, 0.f};
    const float4* e4 = (const float4*)(emb + (size_t)s * An);
    for (int a4 = 0; a4 < An / 4; a4++) {
        float4 e = e4[a4];
#pragma unroll
        for (int c = 0; c < 8; c++)
            acc[c] += e.x * scol[c][4 * a4] + e.y * scol[c][4 * a4 + 1]
                    + e.z * scol[c][4 * a4 + 2] + e.w * scol[c][4 * a4 + 3];
    }
#pragma unroll
    for (int c = 0; c < 8; c++) g_M[s][hbase + c] = acc[c];
}

// ------------- K_gemmP: P[v][s] = Wout_a[v] . emb[s]  (tensor cores) -------------
__global__ void __launch_bounds__(128)
k_gemmP()
{
    const int lane = threadIdx.x & 31, w = threadIdx.x >> 5;
    const int v0 = blockIdx.x * 64 + w * 16;
    const int gid = lane >> 2;
    const int qid = lane & 3;
    const int r0 = min(v0 + gid, Vn - 1);
    const int r1 = min(v0 + gid + 8, Vn - 1);
    const __half* A0 = g_Wh + (size_t)r0 * 2048 + 1024 + 2 * qid;
    const __half* A1 = g_Wh + (size_t)r1 * 2048 + 1024 + 2 * qid;

    float c[16][4];
#pragma unroll
    for (int nt = 0; nt < 16; nt++)
        c[nt][0] = c[nt][1] = c[nt][2] = c[nt][3] = 0.f;

    for (int k0 = 0; k0 < An; k0 += 16) {
        unsigned a0 = *(const unsigned*)(A0 + k0);
        unsigned a1 = *(const unsigned*)(A1 + k0);
        unsigned a2 = *(const unsigned*)(A0 + k0 + 8);
        unsigned a3 = *(const unsigned*)(A1 + k0 + 8);
        const __half* B = g_emb_h + (size_t)gid * An + k0 + 2 * qid;
#pragma unroll
        for (int nt = 0; nt < 16; nt++) {
            unsigned b0 = *(const unsigned*)(B + (size_t)nt * 8 * An);
            unsigned b1 = *(const unsigned*)(B + (size_t)nt * 8 * An + 8);
            asm volatile(
                "mma.sync.aligned.m16n8k16.row.col.f32.f16.f16.f32 "
                "{%0,%1,%2,%3}, {%4,%5,%6,%7}, {%8,%9}, {%0,%1,%2,%3};"
                : "+f"(c[nt][0]), "+f"(c[nt][1]), "+f"(c[nt][2]), "+f"(c[nt][3])
                : "r"(a0), "r"(a1), "r"(a2), "r"(a3), "r"(b0), "r"(b1));
        }
    }
    const int sv0 = v0 + gid, sv1 = v0 + gid + 8;
#pragma unroll
    for (int nt = 0; nt < 16; nt++) {
        int sc_ = nt * 8 + 2 * qid;
        if (sv0 < Vn)
            *(__half2*)&g_P[(size_t)sv0 * Sn + sc_] = __floats2half2_rn(c[nt][0], c[nt][1]);
        if (sv1 < Vn)
            *(__half2*)&g_P[(size_t)sv1 * Sn + sc_] = __floats2half2_rn(c[nt][2], c[nt][3]);
    }
}

// ---- K1: small kernel: finalize + GRU + score partials (exit; no tail wait) ----
__global__ void __launch_bounds__(NTS, 1)
k_small(const float* __restrict__ hidden, const float* __restrict__ emb,
        const float* __restrict__ E, const float* __restrict__ bih,
        const float* __restrict__ bhh, float* __restrict__ out, int step)
{
    const int tid = threadIdx.x, bid = blockIdx.x;
    const int wid = tid >> 5, lane = tid & 31;

    __shared__ float sgi[8][3], sgh[8][3];
    __shared__ float shn[8];

    int word = SOS;
    if (step > 0) {
        unsigned long long best = g_apk[(step - 1) & 1];
        word = (int)(0xFFFFFFFFu - (unsigned)(best & 0xFFFFFFFFull));
        float logZ = logf(g_sum[(step - 1) & 1]);
        if (bid == 0 && tid == 0) {
            g_logZ = logZ;
            out[(size_t)Tn * Vn + (size_t)Tn * Sn + (step - 1)] = (float)word;
        }
        if (step == Tn) {   // tail: finalize last step's log_softmax
            for (int v = bid * NTS + tid; v < Vn; v += NBS * NTS)
                out[(size_t)(step - 1) * Vn + v] -= logZ;
            return;
        }
    }
    if (bid == 0 && tid == 0) { g_apk[step & 1] = 0ull; g_sum[step & 1] = 0.f; }

    const float* h = (step == 0) ? hidden : g_hbuf[(step - 1) & 1];
    float* hn = g_hbuf[step & 1];

    // ===== Phase A: GRU — warp per (unit, gate), fp16 weights ====
    {
        const int ul = wid / 3;
        const int g  = wid % 3;
        const int u  = bid * 8 + ul;
        const int row = g * Hd + u;
        const float4* x4 = (const float4*)(E + (size_t)word * Dm);
        const float4* h4 = (const float4*)h;
        const uint4* wi = (const uint4*)(g_Wih_h + (size_t)row * Dm);
        const uint4* wh = (const uint4*)(g_Whh_h + (size_t)row * Hd);
        float si = 0.f, sh = 0.f;
#pragma unroll
        for (int j = 0; j < 2; j++) {
            int idx = lane + 32 * j;
            si += dot16(wi[idx], x4[2 * idx], x4[2 * idx + 1]);
        }
#pragma unroll
        for (int j = 0; j < 4; j++) {
            int idx = lane + 32 * j;
            sh += dot16(wh[idx], h4[2 * idx], h4[2 * idx + 1]);
        }
        si = warp_sum(si); sh = warp_sum(sh);
        if (lane == 0) { sgi[ul][g] = si + bih[row]; sgh[ul][g] = sh + bhh[row]; }
        __syncthreads();
        if (tid < 8) {
            int u2 = bid * 8 + tid;
            float r = 1.f / (1.f + __expf(-(sgi[tid][0] + sgh[tid][0])));
            float z = 1.f / (1.f + __expf(-(sgi[tid][1] + sgh[tid][1])));
            float n = tanhf(sgi[tid][2] + r * sgh[tid][2]);
            float hv = (1.f - z) * n + z * h[u2];
            hn[u2] = hv;
            shn[tid] = hv;
        }
        __syncthreads();
        // score partials: thread s (<128) dots this block's 8 hn units vs M[s]
        if (tid < Sn) {
            float4 m0 = *(const float4*)&g_M[tid][bid * 8];
            float4 m1 = *(const float4*)&g_M[tid][bid * 8 + 4];
            float p = m0.x*shn[0] + m0.y*shn[1] + m0.z*shn[2] + m0.w*shn[3]
                    + m1.x*shn[4] + m1.y*shn[5] + m1.z*shn[6] + m1.w*shn[7];
            atomicAdd(&g_scoreslot[step & 1][tid], p);
        }
    }

    if (step == 0) {
        // step 0: full barrier + softmax + attn (k_logits0 needs g_attn)
        gsync();
        if (wid < 8) {
            const float* sc = g_scoreslot[0];
            const int d = bid + NBS * wid;
            float sc0 = sc[lane], sc1 = sc[lane + 32];
            float sc2 = sc[lane + 64], sc3 = sc[lane + 96];
            float mx = fmaxf(fmaxf(sc0, sc1), fmaxf(sc2, sc3));
#pragma unroll
            for (int o = 16; o > 0; o >>= 1)
                mx = fmaxf(mx, __shfl_xor_sync(0xffffffffu, mx, o));
            float e0 = __expf(sc0 - mx), e1 = __expf(sc1 - mx);
            float e2 = __expf(sc2 - mx), e3 = __expf(sc3 - mx);
            float ssum = e0 + e1 + e2 + e3;
#pragma unroll
            for (int o = 16; o > 0; o >>= 1)
                ssum += __shfl_xor_sync(0xffffffffu, ssum, o);
            float inv = 1.f / ssum;
            float part = e0 * inv * emb[(size_t)lane * An + d]
                       + e1 * inv * emb[(size_t)(lane + 32) * An + d]
                       + e2 * inv * emb[(size_t)(lane + 64) * An + d]
                       + e3 * inv * emb[(size_t)(lane + 96) * An + d];
            part = warp_sum(part);
            if (lane == 0) g_attn[d] = part;
            if (d == 0) {
                float* wo = out + (size_t)Tn * Vn;
                wo[lane]      = e0 * inv;
                wo[lane + 32] = e1 * inv;
                wo[lane + 64] = e2 * inv;
                wo[lane + 96] = e3 * inv;
            }
        }
    }
    // steps >=1: nothing more — k_logits computes the softmax itself
}

// -- K2: split logits GEMV (steps 1..24): softmax-in-kernel + hn.Wh + w.P --
__global__ void __launch_bounds__(256)
k_logits(const float* __restrict__ bout, float* __restrict__ out, int step)
{
    __shared__ __align__(16) float shn4[Hd];
    __shared__ __align__(16) float sw[Sn];
    __shared__ unsigned long long spk[8];
    __shared__ float sse[8];
    const int tid = threadIdx.x, wid = tid >> 5, lane = tid & 31;
    const float* hn = g_hbuf[step & 1];

    if (blockIdx.x == 0 && tid < Sn) g_scoreslot[(step + 1) & 1][tid] = 0.f;
    if (tid < RPB) {
        int pv = blockIdx.x * RPB + tid;
        if (pv < Vn) out[(size_t)(step - 1) * Vn + pv] -= g_logZ;
    }
    ((float4*)shn4)[tid] = ((const float4*)hn)[tid];
    // warp 0: softmax over the 128 raw scores (complete — stream order)
    if (wid == 0) {
        const float* sc = g_scoreslot[step & 1];
        float sc0 = sc[lane], sc1 = sc[lane + 32];
        float sc2 = sc[lane + 64], sc3 = sc[lane + 96];
        float mx = fmaxf(fmaxf(sc0, sc1), fmaxf(sc2, sc3));
#pragma unroll
        for (int o = 16; o > 0; o >>= 1)
            mx = fmaxf(mx, __shfl_xor_sync(0xffffffffu, mx, o));
        float e0 = __expf(sc0 - mx), e1 = __expf(sc1 - mx);
        float e2 = __expf(sc2 - mx), e3 = __expf(sc3 - mx);
        float ssum = e0 + e1 + e2 + e3;
#pragma unroll
        for (int o = 16; o > 0; o >>= 1)
            ssum += __shfl_xor_sync(0xffffffffu, ssum, o);
        float inv = 1.f / ssum;
        sw[lane]      = e0 * inv;
        sw[lane + 32] = e1 * inv;
        sw[lane + 64] = e2 * inv;
        sw[lane + 96] = e3 * inv;
        if (blockIdx.x == 0) {     // weights output row (once)
            float* wo = out + (size_t)Tn * Vn + (size_t)step * Sn;
            wo[lane]      = e0 * inv;
            wo[lane + 32] = e1 * inv;
            wo[lane + 64] = e2 * inv;
            wo[lane + 96] = e3 * inv;
        }
    }
    __syncthreads();

    const int v0 = blockIdx.x * RPB + wid * 2;
    const int v1 = v0 + 1;
    const bool val0 = (v0 < Vn), val1 = (v1 < Vn);
    const int v0c = val0 ? v0 : (Vn - 1);
    const int v1c = val1 ? v1 : (Vn - 1);
    float s0 = 0.f, s1 = 0.f;
    {
        const uint4* w4a = (const uint4*)(g_Wh + (size_t)v0c * 2048);
        const uint4* w4b = (const uint4*)(g_Wh + (size_t)v1c * 2048);
        const float4* m4 = (const float4*)shn4;
#pragma unroll
        for (int j = 0; j < 4; j++) {
            int idx = lane + 32 * j;
            float4 ma = m4[2 * idx], mb = m4[2 * idx + 1];
            s0 += dot16(w4a[idx], ma, mb);
            s1 += dot16(w4b[idx], ma, mb);
        }
        uint2 p0 = *(const uint2*)(g_P + (size_t)v0c * Sn + lane * 4);
        uint2 p1 = *(const uint2*)(g_P + (size_t)v1c * Sn + lane * 4);
        float4 wv = ((const float4*)sw)[lane];
        float2 q0 = __half22float2(*(const __half2*)&p0.x);
        float2 q1 = __half22float2(*(const __half2*)&p0.y);
        s0 += q0.x * wv.x + q0.y * wv.y + q1.x * wv.z + q1.y * wv.w;
        float2 r0_ = __half22float2(*(const __half2*)&p1.x);
        float2 r1_ = __half22float2(*(const __half2*)&p1.y);
        s1 += r0_.x * wv.x + r0_.y * wv.y + r1_.x * wv.z + r1_.y * wv.w;
    }
    s0 = warp_sum(s0);
    s1 = warp_sum(s1);
    if (lane == 0) {
        float* lp = out + (size_t)step * Vn;
        unsigned long long pk = 0ull;
        float e = 0.f;
        if (val0) {
            float l0 = s0 + bout[v0];
            lp[v0] = l0;
            pk = packkey(l0, v0);
            e = __expf(l0);
        }
        if (val1) {
            float l1 = s1 + bout[v1];
            lp[v1] = l1;
            pk = umaxll(pk, packkey(l1, v1));
            e += __expf(l1);
        }
        spk[wid] = pk; sse[wid] = e;
    }
    __syncthreads();
    if (tid == 0) {
        unsigned long long best = spk[0];
        float tot = sse[0];
#pragma unroll
        for (int i = 1; i < 8; i++) { best = umaxll(best, spk[i]); tot += sse[i]; }
        atomicMax(&g_apk[step & 1], best);
        atomicAdd(&g_sum[step & 1], tot);
    }
}

// -- K2a: step-0 logits from fp32 Wout + fp16 writeback (1 row/warp, 8/block) --
__global__ void __launch_bounds__(256)
k_logits0(const float* __restrict__ Wout, const float* __restrict__ bout,
          float* __restrict__ out)
{
    __shared__ __align__(16) float merge[2 * Hd];
    __shared__ unsigned long long spk[8];
    __shared__ float sse[8];
    const int tid = threadIdx.x, wid = tid >> 5, lane = tid & 31;
    const float* hn = g_hbuf[0];

    if (blockIdx.x == 0 && tid < Sn) g_scoreslot[1][tid] = 0.f;   // slot for step 1
    for (int i = tid; i < Hd; i += 256) { merge[i] = hn[i]; merge[Hd + i] = g_attn[i]; }
    __syncthreads();

    int v = blockIdx.x * 8 + wid;
    float logit = __int_as_float(0xff800000);
    bool valid = (v < Vn);
    if (valid) {
        const float4* w4 = (const float4*)(Wout + (size_t)v * (2 * Hd));
        uint4* wh = (uint4*)(g_Wh + (size_t)v * (2 * Hd));
        const float4* m4 = (const float4*)merge;
        float s = 0.f;
#pragma unroll
        for (int j = 0; j < 8; j++) {
            int idx = lane + 32 * j;
            float4 a = w4[2 * idx], b = w4[2 * idx + 1];
            float4 ma = m4[2 * idx], mb = m4[2 * idx + 1];
            s += a.x*ma.x + a.y*ma.y + a.z*ma.z + a.w*ma.w
               + b.x*mb.x + b.y*mb.y + b.z*mb.z + b.w*mb.w;
            uint4 u;
            ((__half2*)&u)[0] = __floats2half2_rn(a.x, a.y);
            ((__half2*)&u)[1] = __floats2half2_rn(a.z, a.w);
            ((__half2*)&u)[2] = __floats2half2_rn(b.x, b.y);
            ((__half2*)&u)[3] = __floats2half2_rn(b.z, b.w);
            wh[idx] = u;
        }
        s = warp_sum(s);
        if (lane == 0) {
            logit = s + bout[v];
            out[v] = logit;     // step 0 row; logZ subtracted in k_logits(1)
        }
    }
    if (lane == 0) {
        unsigned long long pk = 0ull;
        float e = 0.f;
        if (valid) { pk = packkey(logit, v); e = __expf(logit); }
        spk[wid] = pk; sse[wid] = e;
    }
    __syncthreads();
    if (tid == 0) {
        unsigned long long best = spk[0];
        float tot = sse[0];
#pragma unroll
        for (int i = 1; i < 8; i++) { best = umaxll(best, spk[i]); tot += sse[i]; }
        atomicMax(&g_apk[0], best);
        atomicAdd(&g_sum[0], tot);
    }
}

// ---------------- launcher ----------------
extern "C" void kernel_launch(void* const* d_in, const int* in_sizes, int n_in,
                              void* d_out, int out_size)
{
    const float* hidden = (const float*)d_in[0];
    const float* emb    = (const float*)d_in[1];
    const float* E      = (const float*)d_in[2];
    const float* Wih    = (const float*)d_in[3];
    const float* Whh    = (const float*)d_in[4];
    const float* bih    = (const float*)d_in[5];
    const float* bhh    = (const float*)d_in[6];
    const float* Wq     = (const float*)d_in[7];
    const float* Wout   = (const float*)d_in[8];
    const float* bout   = (const float*)d_in[9];
    float* out = (float*)d_out;

    k_convert<<<512, 256>>>(Wih, Whh);
    k_prep<<<Sn, 128>>>(emb, Wq);
    k_small<<<NBS, NTS>>>(hidden, emb, E, bih, bhh, out, 0);
    k_logits0<<<NB0, 256>>>(Wout, bout, out);     // writes g_Wh fp16
    k_gemmP<<<NBP, 128>>>();                      // P = Wout_a @ emb^T
    for (int t = 1; t < Tn; t++) {
        k_small <<<NBS, NTS>>>(hidden, emb, E, bih, bhh, out, t);
        k_logits<<<NB3, 256>>>(bout, out, t);
    }
    k_small<<<NBS, NTS>>>(hidden, emb, E, bih, bhh, out, Tn);
}